// round 14
// baseline (speedup 1.0000x reference)
#include <cuda_runtime.h>
#include <math.h>

// Problem constants
#define NMAT 16384
#define P 33                  // pitch for the tiny single-warp kernels only
#define NWARPS 4              // warps per block in batched kernels
#define NBLK  (NMAT / 4)      // 4096 blocks (k7: 1 matrix/warp)
#define NBLK2 (NMAT / 8)      // 2048 blocks (k3/k5: 2 matrices/warp, packed eig)
#define SWEEPS_BATCH 5
#define SWEEPS_SINGLE 7

typedef unsigned long long u64;

// ---------------- device scratch (static globals: allowed) ----------------
__device__ float g_part[64 * 1024];
__device__ float g_bm_sq[1024];
__device__ float g_isq[1024];
__device__ float g_GT_part[(size_t)NBLK2 * 1024];  // 8 MB
__device__ float g_Linv[1024];
__device__ float g_LinvT[1024];
__device__ float g_Lw[1024];
__device__ float g_LwT[1024];
__device__ float g_vcT[(size_t)NMAT * 1024];       // 64 MB, transposed [k][i]
__device__ float g_logw[NMAT * 32];
__device__ float g_dist_part[NBLK2];
__device__ float g_factor[1];

// ---------------- packed f32x2 helpers ----------------
__device__ __forceinline__ u64 pk(float x, float y) {
    u64 r; asm("mov.b64 %0,{%1,%2};" : "=l"(r) : "f"(x), "f"(y)); return r;
}
__device__ __forceinline__ void upk(u64 p, float& x, float& y) {
    asm("mov.b64 {%0,%1},%2;" : "=f"(x), "=f"(y) : "l"(p));
}
__device__ __forceinline__ u64 fma2(u64 a, u64 b, u64 c) {
    u64 d; asm("fma.rn.f32x2 %0,%1,%2,%3;" : "=l"(d) : "l"(a), "l"(b), "l"(c)); return d;
}
__device__ __forceinline__ u64 mul2(u64 a, u64 b) {
    u64 d; asm("mul.rn.f32x2 %0,%1,%2;" : "=l"(d) : "l"(a), "l"(b)); return d;
}
__device__ __forceinline__ u64 add2(u64 a, u64 b) {
    u64 d; asm("add.rn.f32x2 %0,%1,%2;" : "=l"(d) : "l"(a), "l"(b)); return d;
}

// ---------------- packed dual-matrix Jacobi (XOR ordering) ----------------
// Thread `lane` holds column `lane` of TWO symmetric matrices in a[0..31]
// (lo/hi halves) and row `lane` of both V's in v[0..31]. csA: per-warp
// u64[64] shared scratch, 16B aligned, holding (c,s) pairs.
__device__ __forceinline__ u64 eig_pk(u64 a[32], u64 v[32],
                                      u64* csA, int lane, int sweeps) {
    const unsigned FULL = 0xffffffffu;
    const u64 SGN2 = 0x8000000080000000ULL;
#pragma unroll
    for (int i = 0; i < 32; i++) v[i] = (i == lane) ? pk(1.f, 1.f) : 0ULL;
    u64 diag2 = a[0], apq2 = a[1];
    int p1 = lane ^ 1;
#pragma unroll
    for (int k = 0; k < 32; k++) {
        diag2 = (k == lane) ? a[k] : diag2;
        apq2  = (k == p1)   ? a[k] : apq2;
    }
    ulonglong2* cs128 = reinterpret_cast<ulonglong2*>(csA);
    for (int sw = 0; sw < sweeps; sw++) {
#pragma unroll
        for (int m = 1; m < 32; m++) {
            int t0i = m; t0i |= t0i >> 1; t0i |= t0i >> 2; t0i |= t0i >> 4;
            const int lmask = t0i >> 1;
            const int mn = (m == 31) ? 1 : (m + 1);
            bool is_lo = lane < (lane ^ m);
            // --- rotation (scalar per half; both lanes of pair identical) ---
            u64 apq_sh = __shfl_xor_sync(FULL, apq2, m);
            u64 apq_s2 = mul2(pk(0.5f, 0.5f), add2(apq2, apq_sh));
            u64 dp2 = __shfl_xor_sync(FULL, diag2, m);
            u64 app2 = is_lo ? diag2 : dp2;
            u64 aqq2 = is_lo ? dp2 : diag2;
            float as0, as1, ap0, ap1, aq0, aq1;
            upk(apq_s2, as0, as1); upk(app2, ap0, ap1); upk(aqq2, aq0, aq1);
            float th0 = __fdividef(aq0 - ap0, 2.f * as0);
            float th1 = __fdividef(aq1 - ap1, 2.f * as1);
            float q0 = fmaf(th0, th0, 1.f), q1 = fmaf(th1, th1, 1.f);
            float sq0 = q0 * rsqrtf(q0),    sq1 = q1 * rsqrtf(q1);
            float tt0 = __fdividef(copysignf(1.f, th0), fabsf(th0) + sq0);
            float tt1 = __fdividef(copysignf(1.f, th1), fabsf(th1) + sq1);
            float te0 = (fabsf(as0) > 1e-12f) ? tt0 : 0.f;
            float te1 = (fabsf(as1) > 1e-12f) ? tt1 : 0.f;
            float c0 = rsqrtf(fmaf(te0, te0, 1.f));
            float c1 = rsqrtf(fmaf(te1, te1, 1.f));
            float s0 = te0 * c0, s1 = te1 * c1;
            u64 c2 = pk(c0, c1);
            u64 s2 = pk(s0, s1);
            u64 t2 = pk(te0, te1);
            u64 tsig = is_lo ? (t2 ^ SGN2) : t2;
            diag2 = fma2(tsig, apq_s2, diag2);       // analytic diag update
            u64 ssg = is_lo ? (s2 ^ SGN2) : s2;
            u64 cg  = c2;
            cs128[lane] = make_ulonglong2(c2, s2);
            __syncwarp();
            // --- row phase on A + V (register-local, packed) ---
#pragma unroll
            for (int k = 0; k < 16; k++) {
                const int i = ((k & ~lmask) << 1) | (k & lmask);
                const int j = i ^ m;
                ulonglong2 cs = cs128[i];
                u64 cc = cs.x, ss = cs.y;
                u64 ms = ss ^ SGN2;
                u64 ai = a[i], aj = a[j];
                a[i] = fma2(cc, ai, mul2(ms, aj));
                a[j] = fma2(ss, ai, mul2(cc, aj));
                u64 vi = v[i], vj = v[j];
                v[i] = fma2(cc, vi, mul2(ms, vj));
                v[j] = fma2(ss, vi, mul2(cc, vj));
            }
            // --- cross-thread column mix of A + apq tracking ---
            u64 napq = apq2;
            int pn = lane ^ mn;
#pragma unroll
            for (int k = 0; k < 32; k++) {
                u64 ax = __shfl_xor_sync(FULL, a[k], m);
                a[k] = fma2(ssg, ax, mul2(cg, a[k]));
                napq = (k == pn) ? a[k] : napq;
            }
            apq2 = napq;
        }
    }
    return diag2;
}

// acc[0..31] = column `lane` of (A @ B); A row-major pitch-32 in 16B-aligned
// shared (vectorized broadcast reads), b[k] = B[k][lane] in registers.
__device__ __forceinline__ void gemm_colA(const float* __restrict__ A,
                                          const float b[32], float acc[32]) {
    const float4* A4 = reinterpret_cast<const float4*>(A);
#pragma unroll
    for (int i = 0; i < 32; i++) {
        float s = 0.f;
#pragma unroll
        for (int k4 = 0; k4 < 8; k4++) {
            float4 av = A4[i * 8 + k4];
            s = fmaf(av.x, b[4 * k4 + 0], s);
            s = fmaf(av.y, b[4 * k4 + 1], s);
            s = fmaf(av.z, b[4 * k4 + 2], s);
            s = fmaf(av.w, b[4 * k4 + 3], s);
        }
        acc[i] = s;
    }
}

// ---------------- scalar Jacobi + helpers for tiny single-warp kernels ----
__device__ __forceinline__ float warp_eig_sym_reg(float a[32], float v[32],
                                                  float2* cs2, int lane, int sweeps) {
    const unsigned FULL = 0xffffffffu;
#pragma unroll
    for (int i = 0; i < 32; i++) v[i] = (i == lane) ? 1.f : 0.f;
    float diag = 0.f, apq = 0.f;
    int p1 = lane ^ 1;
#pragma unroll
    for (int k = 0; k < 32; k++) {
        diag = (k == lane) ? a[k] : diag;
        apq  = (k == p1)   ? a[k] : apq;
    }
    for (int sw = 0; sw < sweeps; sw++) {
#pragma unroll
        for (int m = 1; m < 32; m++) {
            int t0 = m; t0 |= t0 >> 1; t0 |= t0 >> 2; t0 |= t0 >> 4;
            const int lmask = t0 >> 1;
            const int mn = (m == 31) ? 1 : (m + 1);
            bool is_lo = lane < (lane ^ m);
            float apq_s = 0.5f * (apq + __shfl_xor_sync(FULL, apq, m));
            float dp  = __shfl_xor_sync(FULL, diag, m);
            float app = is_lo ? diag : dp;
            float aqq = is_lo ? dp : diag;
            float th  = (aqq - app) / (2.f * apq_s);
            float tt  = copysignf(1.f, th) / (fabsf(th) + sqrtf(fmaf(th, th, 1.f)));
            float t_eff = (fabsf(apq_s) > 1e-12f) ? tt : 0.f;
            float c = rsqrtf(fmaf(t_eff, t_eff, 1.f));
            float s = t_eff * c;
            float s_signed = is_lo ? -s : s;
            float t_signed = is_lo ? -t_eff : t_eff;
            diag = fmaf(t_signed, apq_s, diag);
            cs2[lane] = make_float2(c, s);
            __syncwarp();
#pragma unroll
            for (int k = 0; k < 16; k++) {
                const int i = ((k & ~lmask) << 1) | (k & lmask);
                const int j = i ^ m;
                float2 cs = cs2[i];
                float ci = cs.x, si = cs.y;
                float x = a[i], y = a[j];
                a[i] = ci * x - si * y;
                a[j] = si * x + ci * y;
                float vx = v[i], vy = v[j];
                v[i] = ci * vx - si * vy;
                v[j] = si * vx + ci * vy;
            }
            float napq = apq;
            int pn = lane ^ mn;
#pragma unroll
            for (int k = 0; k < 32; k++) {
                float ax = __shfl_xor_sync(FULL, a[k], m);
                a[k] = fmaf(s_signed, ax, c * a[k]);
                napq = (k == pn) ? a[k] : napq;
            }
            apq = napq;
        }
    }
    return diag;
}

__device__ __forceinline__ void wmm(const float* A, const float* B, float* C, int lane) {
    __syncwarp();
    float col[32];
#pragma unroll
    for (int i = 0; i < 32; i++) col[i] = 0.f;
#pragma unroll 4
    for (int k = 0; k < 32; k++) {
        float b = B[k * P + lane];
#pragma unroll
        for (int i = 0; i < 32; i++) col[i] = fmaf(A[i * P + k], b, col[i]);
    }
    __syncwarp();
#pragma unroll
    for (int i = 0; i < 32; i++) C[i * P + lane] = col[i];
    __syncwarp();
}

__device__ void warp_chol(float* A, int lane) {
    for (int j = 0; j < 32; j++) {
        if (lane == 0) A[j * P + j] = sqrtf(A[j * P + j]);
        __syncwarp();
        float d = A[j * P + j];
        if (lane > j) A[lane * P + j] /= d;
        __syncwarp();
        float ll = (lane > j) ? A[lane * P + j] : 0.f;
        for (int k = j + 1; k < 32; k++) {
            float lkj = A[k * P + j];
            if (lane >= k) A[lane * P + k] -= ll * lkj;
        }
        __syncwarp();
    }
}

__device__ void warp_trisolve(const float* L, float* Y, int lane) {
    for (int i = 0; i < 32; i++) {
        float rhs = (i == lane) ? 1.f : 0.f;
        for (int k = 0; k < i; k++) rhs -= L[i * P + k] * Y[k * P + lane];
        Y[i * P + lane] = rhs / L[i * P + i];
        __syncwarp();
    }
}

// ---------------- K1: partial sums for bm ----------------
__global__ void __launch_bounds__(1024) k1_bm_partial(const float* __restrict__ X) {
    int tid = threadIdx.x;
    const float* base = X + (size_t)blockIdx.x * 256 * 1024 + tid;
    float s = 0.f;
#pragma unroll 4
    for (int b = 0; b < 256; b++) s += base[(size_t)b * 1024];
    g_part[blockIdx.x * 1024 + tid] = s;
}

// ---------------- K2: bm eigh -> bm^{1/2}, bm^{-1/2} (ONE WARP) ----------------
__global__ void __launch_bounds__(32) k2_bm_sqrt() {
    __shared__ float V[32 * P], g[32];
    __shared__ float2 cs2[32];
    int lane = threadIdx.x;
    float a[32], v[32];
#pragma unroll
    for (int i = 0; i < 32; i++) {
        float s = 0.f;
        for (int blk = 0; blk < 64; blk++) s += g_part[blk * 1024 + i * 32 + lane];
        a[i] = s * (1.f / (float)NMAT);
    }
    float diag = warp_eig_sym_reg(a, v, cs2, lane, SWEEPS_SINGLE);
#pragma unroll
    for (int k = 0; k < 32; k++) V[lane * P + k] = v[k];
    g[lane] = sqrtf(diag);
    __syncwarp();
    {
        float col[32];
#pragma unroll
        for (int i = 0; i < 32; i++) col[i] = 0.f;
        for (int k = 0; k < 32; k++) {
            float b = g[k] * V[lane * P + k];
#pragma unroll
            for (int i = 0; i < 32; i++) col[i] = fmaf(V[i * P + k], b, col[i]);
        }
#pragma unroll
        for (int i = 0; i < 32; i++) g_bm_sq[i * 32 + lane] = col[i];
    }
    {
        float col[32];
#pragma unroll
        for (int i = 0; i < 32; i++) col[i] = 0.f;
        for (int k = 0; k < 32; k++) {
            float b = V[lane * P + k] / g[k];
#pragma unroll
            for (int i = 0; i < 32; i++) col[i] = fmaf(V[i * P + k], b, col[i]);
        }
#pragma unroll
        for (int i = 0; i < 32; i++) g_isq[i * 32 + lane] = col[i];
    }
}

// helper: eig-input column for one k3 matrix (scalar GEMMs, R12 style)
__device__ __forceinline__ void inner_col_k3(const float* __restrict__ Xb,
                                             const float* __restrict__ shIsq,
                                             float* mb, int lane, float out[32]) {
#pragma unroll
    for (int i = 0; i < 32; i++) mb[i * 32 + lane] = Xb[i * 32 + lane];
    __syncwarp();
    float breg[32], acc[32];
#pragma unroll
    for (int k = 0; k < 32; k++) breg[k] = shIsq[k * 32 + lane];
    gemm_colA(mb, breg, acc);                 // S = X @ isq
    __syncwarp();
#pragma unroll
    for (int i = 0; i < 32; i++) mb[i * 32 + lane] = acc[i];
    __syncwarp();
#pragma unroll
    for (int k = 0; k < 32; k++) breg[k] = mb[k * 32 + lane];
    gemm_colA(shIsq, breg, out);              // inner = isq @ S
    __syncwarp();
}

// ---------------- K3: XT = log(isq X isq), partial GT sums (packed eig) -----
__global__ void __launch_bounds__(128, 2) k3_logmean(const float* __restrict__ X) {
    __shared__ __align__(16) float shIsq[1024];
    __shared__ __align__(16) u64 buf[NWARPS][1024];   // float view for GEMMs
    __shared__ __align__(16) u64 csA[NWARPS][64];
    __shared__ u64 shG2[NWARPS][32];
    int tid = threadIdx.x, warp = tid >> 5, lane = tid & 31;
    for (int e = tid; e < 1024; e += 128) shIsq[e] = g_isq[e];
    __syncthreads();

    u64* bwu = buf[warp];
    float* bwf = reinterpret_cast<float*>(bwu);
    int b0 = (blockIdx.x * NWARPS + warp) * 2;

    float a0[32], a1[32];
    inner_col_k3(X + (size_t)b0 * 1024, shIsq, bwf, lane, a0);
    inner_col_k3(X + (size_t)(b0 + 1) * 1024, shIsq, bwf, lane, a1);

    u64 a2[32], v2[32];
#pragma unroll
    for (int k = 0; k < 32; k++) a2[k] = pk(a0[k], a1[k]);

    u64 diag2 = eig_pk(a2, v2, csA[warp], lane, SWEEPS_BATCH);
    float d0, d1; upk(diag2, d0, d1);
    shG2[warp][lane] = pk(logf(d0), logf(d1));
#pragma unroll
    for (int k = 0; k < 32; k++) bwu[k * 32 + lane] = v2[k];   // packed VT
    __syncwarp();

    // XT column lane (both matrices): acc[i] = sum_k VT[k][i]*(logw_k*v[k])
    u64 acc2[32];
#pragma unroll
    for (int i = 0; i < 32; i++) acc2[i] = 0ULL;
#pragma unroll
    for (int k = 0; k < 32; k++) {
        u64 bb = mul2(shG2[warp][k], v2[k]);
        const ulonglong2* R = reinterpret_cast<const ulonglong2*>(bwu + k * 32);
#pragma unroll
        for (int i2 = 0; i2 < 16; i2++) {
            ulonglong2 rr = R[i2];
            acc2[2 * i2]     = fma2(rr.x, bb, acc2[2 * i2]);
            acc2[2 * i2 + 1] = fma2(rr.y, bb, acc2[2 * i2 + 1]);
        }
    }
    // park packed XT; deterministic slice-parallel reduce + lo/hi fold
#pragma unroll
    for (int i = 0; i < 32; i++) bwu[i * 32 + lane] = acc2[i];
    __syncthreads();
#pragma unroll
    for (int r = 0; r < 8; r++) {
        int row = warp * 8 + r;
        u64 s0 = buf[0][row * 32 + lane];
        u64 s1 = buf[1][row * 32 + lane];
        u64 s2 = buf[2][row * 32 + lane];
        u64 s3 = buf[3][row * 32 + lane];
        u64 t = add2(add2(add2(s0, s1), s2), s3);
        float lo, hi; upk(t, lo, hi);
        g_GT_part[(size_t)blockIdx.x * 1024 + row * 32 + lane] = lo + hi;
    }
}

// ---------------- K4a: fold 2048 GT partials -> 64 (into g_part) -------------
__global__ void __launch_bounds__(1024) k4a_reduce() {
    int tid = threadIdx.x;
    int blk = blockIdx.x;  // 0..63
    float s = 0.f;
#pragma unroll 4
    for (int j = 0; j < 32; j++)
        s += g_GT_part[(size_t)(blk * 32 + j) * 1024 + tid];
    g_part[blk * 1024 + tid] = s;
}

// ---------------- K4: GT -> batch_mean -> Linv/LinvT; Lw/LwT (ONE WARP) ------
__global__ void __launch_bounds__(32) k4_center(const float* __restrict__ weight) {
    __shared__ float A[32 * P], V[32 * P], M[32 * P], S[32 * P], T[32 * P], g[32];
    __shared__ float2 cs2[32];
    int lane = threadIdx.x;
    float a[32], v[32];
#pragma unroll
    for (int i = 0; i < 32; i++) {
        float s = 0.f;
        for (int blk = 0; blk < 64; blk++) s += g_part[blk * 1024 + i * 32 + lane];
        a[i] = s * (1.f / (float)NMAT);
    }
    float diag = warp_eig_sym_reg(a, v, cs2, lane, SWEEPS_SINGLE);
#pragma unroll
    for (int k = 0; k < 32; k++) V[lane * P + k] = v[k];
    g[lane] = expf(diag);
    __syncwarp();
    {
        float col[32];
#pragma unroll
        for (int i = 0; i < 32; i++) col[i] = 0.f;
        for (int k = 0; k < 32; k++) {
            float b = g[k] * V[lane * P + k];
#pragma unroll
            for (int i = 0; i < 32; i++) col[i] = fmaf(V[i * P + k], b, col[i]);
        }
#pragma unroll
        for (int i = 0; i < 32; i++) M[i * P + lane] = col[i];
    }
    __syncwarp();
#pragma unroll
    for (int i = 0; i < 32; i++) S[i * P + lane] = g_bm_sq[i * 32 + lane];
    __syncwarp();
    wmm(S, M, T, lane);
    wmm(T, S, A, lane);          // A = batch_mean
    warp_chol(A, lane);
    warp_trisolve(A, T, lane);   // T = L^{-1}
#pragma unroll
    for (int i = 0; i < 32; i++) {
        float lv  = (lane <= i) ? T[i * P + lane] : 0.f;
        g_Linv[i * 32 + lane] = lv;
        float lvt = (i <= lane) ? T[lane * P + i] : 0.f;
        g_LinvT[i * 32 + lane] = lvt;
    }
#pragma unroll
    for (int i = 0; i < 32; i++) M[i * P + lane] = weight[i * 32 + lane];
    __syncwarp();
    warp_chol(M, lane);
#pragma unroll
    for (int i = 0; i < 32; i++) {
        float lv  = (lane <= i) ? M[i * P + lane] : 0.f;
        g_Lw[i * 32 + lane] = lv;
        float lvt = (i <= lane) ? M[lane * P + i] : 0.f;
        g_LwT[i * 32 + lane] = lvt;
    }
}

// helper: eig-input column for one k5 matrix (scalar GEMMs)
__device__ __forceinline__ void inner_col_k5(const float* __restrict__ Xb,
                                             const float* __restrict__ shLinv,
                                             const float* __restrict__ shLinvT,
                                             float* mb, int lane, float out[32]) {
#pragma unroll
    for (int i = 0; i < 32; i++) mb[i * 32 + lane] = Xb[i * 32 + lane];
    __syncwarp();
    float breg[32], acc[32];
#pragma unroll
    for (int k = 0; k < 32; k++) breg[k] = shLinvT[k * 32 + lane];
    gemm_colA(mb, breg, acc);                 // S = X @ Linv^T
    __syncwarp();
#pragma unroll
    for (int i = 0; i < 32; i++) mb[i * 32 + lane] = acc[i];
    __syncwarp();
#pragma unroll
    for (int k = 0; k < 32; k++) breg[k] = mb[k * 32 + lane];
    gemm_colA(shLinv, breg, out);             // Xc = Linv @ S
    __syncwarp();
}

// ---------------- K5: Xc eig (packed), store vcT/logw, variance --------------
__global__ void __launch_bounds__(128, 2) k5_center_eig(const float* __restrict__ X) {
    __shared__ __align__(16) float shLinv[1024];
    __shared__ __align__(16) float shLinvT[1024];
    __shared__ __align__(16) u64 buf[NWARPS][1024];
    __shared__ __align__(16) u64 csA[NWARPS][64];
    __shared__ float shRed[NWARPS];
    int tid = threadIdx.x, warp = tid >> 5, lane = tid & 31;
    for (int e = tid; e < 1024; e += 128) {
        shLinv[e] = g_Linv[e];
        shLinvT[e] = g_LinvT[e];
    }
    __syncthreads();

    float* bwf = reinterpret_cast<float*>(buf[warp]);
    int b0 = (blockIdx.x * NWARPS + warp) * 2;

    float a0[32], a1[32];
    inner_col_k5(X + (size_t)b0 * 1024, shLinv, shLinvT, bwf, lane, a0);
    inner_col_k5(X + (size_t)(b0 + 1) * 1024, shLinv, shLinvT, bwf, lane, a1);

    u64 a2[32], v2[32];
#pragma unroll
    for (int k = 0; k < 32; k++) a2[k] = pk(a0[k], a1[k]);

    u64 diag2 = eig_pk(a2, v2, csA[warp], lane, SWEEPS_BATCH);

    // store eigenvectors transposed, both matrices, straight from registers
    float* vt = g_vcT + (size_t)b0 * 1024;
#pragma unroll
    for (int k = 0; k < 32; k++) {
        float x, y; upk(v2[k], x, y);
        vt[k * 32 + lane] = x;
        vt[1024 + k * 32 + lane] = y;
    }
    float d0, d1; upk(diag2, d0, d1);
    float lw0 = logf(d0), lw1 = logf(d1);
    g_logw[b0 * 32 + lane] = lw0;
    g_logw[(b0 + 1) * 32 + lane] = lw1;

    float d = lw0 * lw0 + lw1 * lw1;
#pragma unroll
    for (int off = 16; off; off >>= 1) d += __shfl_xor_sync(0xffffffffu, d, off);
    if (lane == 0) shRed[warp] = d;
    __syncthreads();
    if (tid == 0) {
        float t = 0.f;
        for (int w = 0; w < NWARPS; w++) t += shRed[w];
        g_dist_part[blockIdx.x] = t;
    }
}

// ---------------- K6: scalar factor ----------------
__global__ void __launch_bounds__(256) k6_factor(const float* __restrict__ shift) {
    __shared__ float sh[256];
    int tid = threadIdx.x;
    float s = 0.f;
    for (int i = tid; i < NBLK2; i += 256) s += g_dist_part[i];
    sh[tid] = s;
    __syncthreads();
    for (int st = 128; st; st >>= 1) {
        if (tid < st) sh[tid] += sh[tid + st];
        __syncthreads();
    }
    if (tid == 0) {
        float var = sh[0] * (1.f / (float)NMAT);
        g_factor[0] = shift[0] / sqrtf(var + 1e-5f);
    }
}

// ---------------- K7: Xs = vc e^{f logw} vc^T; out = Lw Xs Lw^T (scalar) -----
__global__ void __launch_bounds__(128, 4) k7_output(float* __restrict__ out) {
    __shared__ __align__(16) float shLw[1024];
    __shared__ __align__(16) float shLwT[1024];
    __shared__ __align__(16) float buf[NWARPS][1024];  // VT -> Xs -> W
    __shared__ float shG[NWARPS][32];
    int tid = threadIdx.x, warp = tid >> 5, lane = tid & 31;
    for (int e = tid; e < 1024; e += 128) {
        shLw[e] = g_Lw[e];
        shLwT[e] = g_LwT[e];
    }
    __syncthreads();

    float* bw = buf[warp];
    int b = blockIdx.x * NWARPS + warp;
    float factor = g_factor[0];
    const float* vt = g_vcT + (size_t)b * 1024;
    float v[32];
#pragma unroll
    for (int k = 0; k < 32; k++) {
        float val = vt[k * 32 + lane];
        bw[k * 32 + lane] = val;
        v[k] = val;
    }
    shG[warp][lane] = expf(factor * g_logw[b * 32 + lane]);
    __syncwarp();

    // Xs column lane
    float acc[32];
    const float4* V4 = reinterpret_cast<const float4*>(bw);
#pragma unroll
    for (int i = 0; i < 32; i++) acc[i] = 0.f;
#pragma unroll
    for (int k = 0; k < 32; k++) {
        float bb = shG[warp][k] * v[k];
#pragma unroll
        for (int i4 = 0; i4 < 8; i4++) {
            float4 vv = V4[k * 8 + i4];
            acc[4 * i4 + 0] = fmaf(vv.x, bb, acc[4 * i4 + 0]);
            acc[4 * i4 + 1] = fmaf(vv.y, bb, acc[4 * i4 + 1]);
            acc[4 * i4 + 2] = fmaf(vv.z, bb, acc[4 * i4 + 2]);
            acc[4 * i4 + 3] = fmaf(vv.w, bb, acc[4 * i4 + 3]);
        }
    }
    __syncwarp();
#pragma unroll
    for (int i = 0; i < 32; i++) bw[i * 32 + lane] = acc[i];  // buf = Xs
    __syncwarp();

    float breg[32];
#pragma unroll
    for (int k = 0; k < 32; k++) breg[k] = shLwT[k * 32 + lane];
    gemm_colA(bw, breg, acc);                 // W = Xs @ Lw^T
    __syncwarp();
#pragma unroll
    for (int i = 0; i < 32; i++) bw[i * 32 + lane] = acc[i];  // buf = W
    __syncwarp();

#pragma unroll
    for (int k = 0; k < 32; k++) breg[k] = bw[k * 32 + lane];
    gemm_colA(shLw, breg, acc);               // out = Lw @ W

    float* ob = out + (size_t)b * 1024;
#pragma unroll
    for (int i = 0; i < 32; i++) ob[i * 32 + lane] = acc[i];
}

// ---------------- launch ----------------
extern "C" void kernel_launch(void* const* d_in, const int* in_sizes, int n_in,
                              void* d_out, int out_size) {
    (void)in_sizes; (void)n_in; (void)out_size;
    const float* X = (const float*)d_in[0];
    const float* weight = (const float*)d_in[1];
    const float* shift = (const float*)d_in[2];
    float* out = (float*)d_out;

    k1_bm_partial<<<64, 1024>>>(X);
    k2_bm_sqrt<<<1, 32>>>();
    k3_logmean<<<NBLK2, 128>>>(X);
    k4a_reduce<<<64, 1024>>>();
    k4_center<<<1, 32>>>(weight);
    k5_center_eig<<<NBLK2, 128>>>(X);
    k6_factor<<<1, 256>>>(shift);
    k7_output<<<NBLK, 128>>>(out);
}

// round 15
// speedup vs baseline: 1.3565x; 1.3565x over previous
#include <cuda_runtime.h>
#include <math.h>

// Problem constants
#define NMAT 16384
#define P 33                 // pitch for the tiny single-warp kernels only
#define NWARPS 4             // warps per block in batched kernels
#define NBLK (NMAT / NWARPS) // 4096 blocks, 1 matrix per warp
#define SWEEPS_BATCH 5
#define SWEEPS_SINGLE 7

// ---------------- device scratch (static globals: allowed) ----------------
__device__ float g_part[64 * 1024];          // bm partial sums / reduced GT partials
__device__ float g_bm_sq[1024];              // bm^{1/2}
__device__ float g_isq[1024];                // bm^{-1/2} (symmetric)
__device__ float g_GT_part[(size_t)NBLK * 1024]; // 16 MB: XT partial sums
__device__ float g_Linv[1024];               // L^{-1} row-major (lower, upper=0)
__device__ float g_LinvT[1024];              // L^{-T} row-major
__device__ float g_Lw[1024];                 // chol(weight) row-major
__device__ float g_LwT[1024];                // Lw^T row-major
__device__ float g_vcT[(size_t)NMAT * 1024]; // 64 MB: eigenvectors of Xc, TRANSPOSED: [k][i]
__device__ float g_logw[NMAT * 32];          // log eigenvalues of Xc
__device__ float g_dist_part[NBLK];          // Frechet variance partials
__device__ float g_factor[1];

// ---------------- register-resident Jacobi (XOR ordering) ----------------
// Thread `lane` holds column `lane` of symmetric A in a[0..31] and ROW `lane`
// of V in v[0..31]. Returns eigenvalue for eigenvector column `lane`.
// cs2: per-warp 32-entry float2 scratch in shared (coefficient broadcast).
// Fast-math rotation (__fdividef, q*rsqrt(q)) — validated in R13/R14:
// rel_err 1.0412e-4 vs 1.0440e-4 with full-precision ops.
__device__ __forceinline__ float warp_eig_sym_reg(float a[32], float v[32],
                                                  float2* cs2, int lane, int sweeps) {
    const unsigned FULL = 0xffffffffu;
#pragma unroll
    for (int i = 0; i < 32; i++) v[i] = (i == lane) ? 1.f : 0.f;
    float diag = 0.f, apq = 0.f;
    int p1 = lane ^ 1;
#pragma unroll
    for (int k = 0; k < 32; k++) {
        diag = (k == lane) ? a[k] : diag;
        apq  = (k == p1)   ? a[k] : apq;
    }
    for (int sw = 0; sw < sweeps; sw++) {
#pragma unroll
        for (int m = 1; m < 32; m++) {
            int t0 = m; t0 |= t0 >> 1; t0 |= t0 >> 2; t0 |= t0 >> 4;
            const int lmask = t0 >> 1;
            const int mn = (m == 31) ? 1 : (m + 1);
            bool is_lo = lane < (lane ^ m);
            // --- rotation (both lanes of the pair compute identically) ---
            float apq_s = 0.5f * (apq + __shfl_xor_sync(FULL, apq, m));
            float dp  = __shfl_xor_sync(FULL, diag, m);
            float app = is_lo ? diag : dp;
            float aqq = is_lo ? dp : diag;
            float th  = __fdividef(aqq - app, 2.f * apq_s);
            float q   = fmaf(th, th, 1.f);
            float sq  = q * rsqrtf(q);           // sqrt(th^2+1), MUFU-only
            float tt  = __fdividef(copysignf(1.f, th), fabsf(th) + sq);
            float t_eff = (fabsf(apq_s) > 1e-12f) ? tt : 0.f;
            float c = rsqrtf(fmaf(t_eff, t_eff, 1.f));
            float s = t_eff * c;
            float s_signed = is_lo ? -s : s;
            float t_signed = is_lo ? -t_eff : t_eff;
            diag = fmaf(t_signed, apq_s, diag);   // analytic diag update
            // stage coefficients for row-phase broadcast
            cs2[lane] = make_float2(c, s);
            __syncwarp();
            // --- register-local: row mix of A (J^T A) + column mix of V (V J) ---
#pragma unroll
            for (int k = 0; k < 16; k++) {
                const int i = ((k & ~lmask) << 1) | (k & lmask);
                const int j = i ^ m;
                float2 cs = cs2[i];
                float ci = cs.x, si = cs.y;
                float x = a[i], y = a[j];
                a[i] = ci * x - si * y;
                a[j] = si * x + ci * y;
                float vx = v[i], vy = v[j];
                v[i] = ci * vx - si * vy;
                v[j] = si * vx + ci * vy;
            }
            // --- cross-thread column mix of A (A J) + next-round apq tracking ---
            float napq = apq;
            int pn = lane ^ mn;
#pragma unroll
            for (int k = 0; k < 32; k++) {
                float ax = __shfl_xor_sync(FULL, a[k], m);
                a[k] = fmaf(s_signed, ax, c * a[k]);
                napq = (k == pn) ? a[k] : napq;
            }
            apq = napq;
        }
    }
    return diag;
}

// acc[0..31] = column `lane` of (A @ B) where A is 32x32 row-major pitch-32
// (16B-aligned shared) read via vectorized broadcast, b[k] = B[k][lane] in regs.
__device__ __forceinline__ void gemm_colA(const float* __restrict__ A,
                                          const float b[32], float acc[32]) {
    const float4* A4 = reinterpret_cast<const float4*>(A);
#pragma unroll
    for (int i = 0; i < 32; i++) {
        float s = 0.f;
#pragma unroll
        for (int k4 = 0; k4 < 8; k4++) {
            float4 av = A4[i * 8 + k4];
            s = fmaf(av.x, b[4 * k4 + 0], s);
            s = fmaf(av.y, b[4 * k4 + 1], s);
            s = fmaf(av.z, b[4 * k4 + 2], s);
            s = fmaf(av.w, b[4 * k4 + 3], s);
        }
        acc[i] = s;
    }
}

// ---- old pitch-33 helpers (tiny single-warp kernels only) ----
__device__ __forceinline__ void wmm(const float* A, const float* B, float* C, int lane) {
    __syncwarp();
    float col[32];
#pragma unroll
    for (int i = 0; i < 32; i++) col[i] = 0.f;
#pragma unroll 4
    for (int k = 0; k < 32; k++) {
        float b = B[k * P + lane];
#pragma unroll
        for (int i = 0; i < 32; i++) col[i] = fmaf(A[i * P + k], b, col[i]);
    }
    __syncwarp();
#pragma unroll
    for (int i = 0; i < 32; i++) C[i * P + lane] = col[i];
    __syncwarp();
}

__device__ void warp_chol(float* A, int lane) {
    for (int j = 0; j < 32; j++) {
        if (lane == 0) A[j * P + j] = sqrtf(A[j * P + j]);
        __syncwarp();
        float d = A[j * P + j];
        if (lane > j) A[lane * P + j] /= d;
        __syncwarp();
        float ll = (lane > j) ? A[lane * P + j] : 0.f;
        for (int k = j + 1; k < 32; k++) {
            float lkj = A[k * P + j];
            if (lane >= k) A[lane * P + k] -= ll * lkj;
        }
        __syncwarp();
    }
}

__device__ void warp_trisolve(const float* L, float* Y, int lane) {
    for (int i = 0; i < 32; i++) {
        float rhs = (i == lane) ? 1.f : 0.f;
        for (int k = 0; k < i; k++) rhs -= L[i * P + k] * Y[k * P + lane];
        Y[i * P + lane] = rhs / L[i * P + i];
        __syncwarp();
    }
}

// ---------------- K1: partial sums for bm ----------------
__global__ void __launch_bounds__(1024) k1_bm_partial(const float* __restrict__ X) {
    int tid = threadIdx.x;
    const float* base = X + (size_t)blockIdx.x * 256 * 1024 + tid;
    float s = 0.f;
#pragma unroll 4
    for (int b = 0; b < 256; b++) s += base[(size_t)b * 1024];
    g_part[blockIdx.x * 1024 + tid] = s;
}

// ---------------- K2: bm eigh -> bm^{1/2}, bm^{-1/2} (ONE WARP) ----------------
__global__ void __launch_bounds__(32) k2_bm_sqrt() {
    __shared__ float V[32 * P], g[32];
    __shared__ float2 cs2[32];
    int lane = threadIdx.x;
    float a[32], v[32];
#pragma unroll
    for (int i = 0; i < 32; i++) {
        float s = 0.f;
        for (int blk = 0; blk < 64; blk++) s += g_part[blk * 1024 + i * 32 + lane];
        a[i] = s * (1.f / (float)NMAT);
    }
    float diag = warp_eig_sym_reg(a, v, cs2, lane, SWEEPS_SINGLE);
#pragma unroll
    for (int k = 0; k < 32; k++) V[lane * P + k] = v[k];
    g[lane] = sqrtf(diag);
    __syncwarp();
    {   // bm_sq = V diag(sw) V^T
        float col[32];
#pragma unroll
        for (int i = 0; i < 32; i++) col[i] = 0.f;
        for (int k = 0; k < 32; k++) {
            float b = g[k] * V[lane * P + k];
#pragma unroll
            for (int i = 0; i < 32; i++) col[i] = fmaf(V[i * P + k], b, col[i]);
        }
#pragma unroll
        for (int i = 0; i < 32; i++) g_bm_sq[i * 32 + lane] = col[i];
    }
    {   // bm_isq = V diag(1/sw) V^T
        float col[32];
#pragma unroll
        for (int i = 0; i < 32; i++) col[i] = 0.f;
        for (int k = 0; k < 32; k++) {
            float b = V[lane * P + k] / g[k];
#pragma unroll
            for (int i = 0; i < 32; i++) col[i] = fmaf(V[i * P + k], b, col[i]);
        }
#pragma unroll
        for (int i = 0; i < 32; i++) g_isq[i * 32 + lane] = col[i];
    }
}

// ---------------- K3: XT = log(isq X isq), partial GT sums ----------------
__global__ void __launch_bounds__(128, 4) k3_logmean(const float* __restrict__ X) {
    __shared__ __align__(16) float shIsq[1024];
    __shared__ __align__(16) float buf[NWARPS][1024];   // X -> S -> VT -> acc
    __shared__ float2 cs2s[NWARPS][32];
    __shared__ float shG[NWARPS][32];
    int tid = threadIdx.x, warp = tid >> 5, lane = tid & 31;
    for (int e = tid; e < 1024; e += 128) shIsq[e] = g_isq[e];
    __syncthreads();

    float* bw = buf[warp];
    int b = blockIdx.x * NWARPS + warp;
    const float* Xb = X + (size_t)b * 1024;
#pragma unroll
    for (int i = 0; i < 32; i++) bw[i * 32 + lane] = Xb[i * 32 + lane];
    __syncwarp();

    // S = X @ isq
    float breg[32], acc[32];
#pragma unroll
    for (int k = 0; k < 32; k++) breg[k] = shIsq[k * 32 + lane];
    gemm_colA(bw, breg, acc);
    __syncwarp();
#pragma unroll
    for (int i = 0; i < 32; i++) bw[i * 32 + lane] = acc[i];  // buf = S
    __syncwarp();

    // inner = isq @ S
    float a[32], v[32];
#pragma unroll
    for (int k = 0; k < 32; k++) breg[k] = bw[k * 32 + lane];
    gemm_colA(shIsq, breg, a);
    __syncwarp();

    float diag = warp_eig_sym_reg(a, v, cs2s[warp], lane, SWEEPS_BATCH);

    // store V transposed: buf[k][lane] = v[k]
#pragma unroll
    for (int k = 0; k < 32; k++) bw[k * 32 + lane] = v[k];
    shG[warp][lane] = logf(diag);
    __syncwarp();

    // XT column lane: acc[i] = sum_k VT[k][i] * (logw_k * v[k])
    const float4* V4 = reinterpret_cast<const float4*>(bw);
#pragma unroll
    for (int i = 0; i < 32; i++) acc[i] = 0.f;
#pragma unroll
    for (int k = 0; k < 32; k++) {
        float bb = shG[warp][k] * v[k];
#pragma unroll
        for (int i4 = 0; i4 < 8; i4++) {
            float4 vv = V4[k * 8 + i4];
            acc[4 * i4 + 0] = fmaf(vv.x, bb, acc[4 * i4 + 0]);
            acc[4 * i4 + 1] = fmaf(vv.y, bb, acc[4 * i4 + 1]);
            acc[4 * i4 + 2] = fmaf(vv.z, bb, acc[4 * i4 + 2]);
            acc[4 * i4 + 3] = fmaf(vv.w, bb, acc[4 * i4 + 3]);
        }
    }
    // park each warp's XT in its own buffer (VT no longer needed)
#pragma unroll
    for (int i = 0; i < 32; i++) bw[i * 32 + lane] = acc[i];
    __syncthreads();
    // deterministic slice-parallel reduction: warp w sums rows [8w, 8w+8)
#pragma unroll
    for (int r = 0; r < 8; r++) {
        int row = warp * 8 + r;
        float s0 = buf[0][row * 32 + lane];
        float s1 = buf[1][row * 32 + lane];
        float s2 = buf[2][row * 32 + lane];
        float s3 = buf[3][row * 32 + lane];
        g_GT_part[(size_t)blockIdx.x * 1024 + row * 32 + lane] = ((s0 + s1) + s2) + s3;
    }
}

// ---------------- K4a: fold 4096 GT partials -> 64 (into g_part) ----------------
__global__ void __launch_bounds__(1024) k4a_reduce() {
    int tid = threadIdx.x;
    int blk = blockIdx.x;  // 0..63
    float s = 0.f;
#pragma unroll 4
    for (int j = 0; j < 64; j++)
        s += g_GT_part[(size_t)(blk * 64 + j) * 1024 + tid];
    g_part[blk * 1024 + tid] = s;
}

// ---------------- K4: GT -> batch_mean -> Linv/LinvT; Lw/LwT (ONE WARP) ----
__global__ void __launch_bounds__(32) k4_center(const float* __restrict__ weight) {
    __shared__ float A[32 * P], V[32 * P], M[32 * P], S[32 * P], T[32 * P], g[32];
    __shared__ float2 cs2[32];
    int lane = threadIdx.x;
    float a[32], v[32];
#pragma unroll
    for (int i = 0; i < 32; i++) {
        float s = 0.f;
        for (int blk = 0; blk < 64; blk++) s += g_part[blk * 1024 + i * 32 + lane];
        a[i] = s * (1.f / (float)NMAT);
    }
    float diag = warp_eig_sym_reg(a, v, cs2, lane, SWEEPS_SINGLE);
#pragma unroll
    for (int k = 0; k < 32; k++) V[lane * P + k] = v[k];
    g[lane] = expf(diag);
    __syncwarp();
    {   // M = expm(GT) = V diag(e) V^T
        float col[32];
#pragma unroll
        for (int i = 0; i < 32; i++) col[i] = 0.f;
        for (int k = 0; k < 32; k++) {
            float b = g[k] * V[lane * P + k];
#pragma unroll
            for (int i = 0; i < 32; i++) col[i] = fmaf(V[i * P + k], b, col[i]);
        }
#pragma unroll
        for (int i = 0; i < 32; i++) M[i * P + lane] = col[i];
    }
    __syncwarp();
#pragma unroll
    for (int i = 0; i < 32; i++) S[i * P + lane] = g_bm_sq[i * 32 + lane];
    __syncwarp();
    wmm(S, M, T, lane);  // bm_sq @ expm(GT)
    wmm(T, S, A, lane);  // A = batch_mean
    warp_chol(A, lane);
    warp_trisolve(A, T, lane);  // T = L^{-1}
#pragma unroll
    for (int i = 0; i < 32; i++) {
        float lv = (lane <= i) ? T[i * P + lane] : 0.f;   // Linv[i][lane]
        g_Linv[i * 32 + lane] = lv;
        float lvt = (i <= lane) ? T[lane * P + i] : 0.f;  // LinvT[i][lane]
        g_LinvT[i * 32 + lane] = lvt;
    }
    // Lw = chol(weight)
#pragma unroll
    for (int i = 0; i < 32; i++) M[i * P + lane] = weight[i * 32 + lane];
    __syncwarp();
    warp_chol(M, lane);
#pragma unroll
    for (int i = 0; i < 32; i++) {
        float lv = (lane <= i) ? M[i * P + lane] : 0.f;   // Lw[i][lane]
        g_Lw[i * 32 + lane] = lv;
        float lvt = (i <= lane) ? M[lane * P + i] : 0.f;  // LwT[i][lane]
        g_LwT[i * 32 + lane] = lvt;
    }
}

// ---------------- K5: Xc eig, store vcT/logw, variance partials ----------------
__global__ void __launch_bounds__(128, 4) k5_center_eig(const float* __restrict__ X) {
    __shared__ __align__(16) float shLinv[1024];
    __shared__ __align__(16) float shLinvT[1024];
    __shared__ __align__(16) float buf[NWARPS][1024];   // X -> S
    __shared__ float2 cs2s[NWARPS][32];
    __shared__ float shRed[NWARPS];
    int tid = threadIdx.x, warp = tid >> 5, lane = tid & 31;
    for (int e = tid; e < 1024; e += 128) {
        shLinv[e] = g_Linv[e];
        shLinvT[e] = g_LinvT[e];
    }
    __syncthreads();

    float* bw = buf[warp];
    int b = blockIdx.x * NWARPS + warp;
    const float* Xb = X + (size_t)b * 1024;
#pragma unroll
    for (int i = 0; i < 32; i++) bw[i * 32 + lane] = Xb[i * 32 + lane];
    __syncwarp();

    // S = X @ Linv^T
    float breg[32], acc[32];
#pragma unroll
    for (int k = 0; k < 32; k++) breg[k] = shLinvT[k * 32 + lane];
    gemm_colA(bw, breg, acc);
    __syncwarp();
#pragma unroll
    for (int i = 0; i < 32; i++) bw[i * 32 + lane] = acc[i];  // buf = S
    __syncwarp();

    // Xc = Linv @ S
    float a[32], v[32];
#pragma unroll
    for (int k = 0; k < 32; k++) breg[k] = bw[k * 32 + lane];
    gemm_colA(shLinv, breg, a);

    float diag = warp_eig_sym_reg(a, v, cs2s[warp], lane, SWEEPS_BATCH);

    // write eigenvectors transposed, coalesced straight from registers
    float* vt = g_vcT + (size_t)b * 1024;
#pragma unroll
    for (int k = 0; k < 32; k++) vt[k * 32 + lane] = v[k];

    float lw = logf(diag);
    g_logw[b * 32 + lane] = lw;

    float d = lw * lw;
#pragma unroll
    for (int off = 16; off; off >>= 1) d += __shfl_xor_sync(0xffffffffu, d, off);
    if (lane == 0) shRed[warp] = d;
    __syncthreads();
    if (tid == 0) {
        float t = 0.f;
        for (int w = 0; w < NWARPS; w++) t += shRed[w];
        g_dist_part[blockIdx.x] = t;
    }
}

// ---------------- K6: scalar factor ----------------
__global__ void __launch_bounds__(256) k6_factor(const float* __restrict__ shift) {
    __shared__ float sh[256];
    int tid = threadIdx.x;
    float s = 0.f;
    for (int i = tid; i < NBLK; i += 256) s += g_dist_part[i];
    sh[tid] = s;
    __syncthreads();
    for (int st = 128; st; st >>= 1) {
        if (tid < st) sh[tid] += sh[tid + st];
        __syncthreads();
    }
    if (tid == 0) {
        float var = sh[0] * (1.f / (float)NMAT);
        g_factor[0] = shift[0] / sqrtf(var + 1e-5f);
    }
}

// ---------------- K7: Xs = vc e^{f logw} vc^T; out = Lw Xs Lw^T ----------------
__global__ void __launch_bounds__(128, 4) k7_output(float* __restrict__ out) {
    __shared__ __align__(16) float shLw[1024];
    __shared__ __align__(16) float shLwT[1024];
    __shared__ __align__(16) float buf[NWARPS][1024];  // VT -> Xs -> W
    __shared__ float shG[NWARPS][32];
    int tid = threadIdx.x, warp = tid >> 5, lane = tid & 31;
    for (int e = tid; e < 1024; e += 128) {
        shLw[e] = g_Lw[e];
        shLwT[e] = g_LwT[e];
    }
    __syncthreads();

    float* bw = buf[warp];
    int b = blockIdx.x * NWARPS + warp;
    float factor = g_factor[0];
    const float* vt = g_vcT + (size_t)b * 1024;
    float v[32];
#pragma unroll
    for (int k = 0; k < 32; k++) {        // coalesced; also yields v[k] = VT[k][lane]
        float val = vt[k * 32 + lane];
        bw[k * 32 + lane] = val;
        v[k] = val;
    }
    shG[warp][lane] = expf(factor * g_logw[b * 32 + lane]);
    __syncwarp();

    // Xs column lane: acc[i] = sum_k VT[k][i] * (e_k * v[k])
    float acc[32];
    const float4* V4 = reinterpret_cast<const float4*>(bw);
#pragma unroll
    for (int i = 0; i < 32; i++) acc[i] = 0.f;
#pragma unroll
    for (int k = 0; k < 32; k++) {
        float bb = shG[warp][k] * v[k];
#pragma unroll
        for (int i4 = 0; i4 < 8; i4++) {
            float4 vv = V4[k * 8 + i4];
            acc[4 * i4 + 0] = fmaf(vv.x, bb, acc[4 * i4 + 0]);
            acc[4 * i4 + 1] = fmaf(vv.y, bb, acc[4 * i4 + 1]);
            acc[4 * i4 + 2] = fmaf(vv.z, bb, acc[4 * i4 + 2]);
            acc[4 * i4 + 3] = fmaf(vv.w, bb, acc[4 * i4 + 3]);
        }
    }
    __syncwarp();
#pragma unroll
    for (int i = 0; i < 32; i++) bw[i * 32 + lane] = acc[i];  // buf = Xs
    __syncwarp();

    // W = Xs @ Lw^T
    float breg[32];
#pragma unroll
    for (int k = 0; k < 32; k++) breg[k] = shLwT[k * 32 + lane];
    gemm_colA(bw, breg, acc);
    __syncwarp();
#pragma unroll
    for (int i = 0; i < 32; i++) bw[i * 32 + lane] = acc[i];  // buf = W
    __syncwarp();

    // out = Lw @ W
#pragma unroll
    for (int k = 0; k < 32; k++) breg[k] = bw[k * 32 + lane];
    gemm_colA(shLw, breg, acc);

    float* ob = out + (size_t)b * 1024;
#pragma unroll
    for (int i = 0; i < 32; i++) ob[i * 32 + lane] = acc[i];
}

// ---------------- launch ----------------
extern "C" void kernel_launch(void* const* d_in, const int* in_sizes, int n_in,
                              void* d_out, int out_size) {
    (void)in_sizes; (void)n_in; (void)out_size;
    const float* X = (const float*)d_in[0];
    const float* weight = (const float*)d_in[1];
    const float* shift = (const float*)d_in[2];
    float* out = (float*)d_out;

    k1_bm_partial<<<64, 1024>>>(X);
    k2_bm_sqrt<<<1, 32>>>();
    k3_logmean<<<NBLK, 128>>>(X);
    k4a_reduce<<<64, 1024>>>();
    k4_center<<<1, 32>>>(weight);
    k5_center_eig<<<NBLK, 128>>>(X);
    k6_factor<<<1, 256>>>(shift);
    k7_output<<<NBLK, 128>>>(out);
}